// round 8
// baseline (speedup 1.0000x reference)
#include <cuda_runtime.h>

#define B_SZ 16
#define N_PTS 4096
#define K_NN 20
#define CO 64
#define KNN_BLOCKS 128
#define NVALS 27
#define CAP 32          // per-lane smem stack capacity (4B slots)
#define NCHUNK 14
#define SLACK 2e-3f

// ---------------- scratch (static device allocations, allowed) ----------------
__device__ int    g_idx[B_SZ * N_PTS * K_NN];       // 5.24 MB
__device__ double g_part[KNN_BLOCKS * NVALS];
__device__ float  g_scale[CO];
__device__ float  g_shift[CO];

// packed f32x2 helpers (sm_100+ PTX)
__device__ __forceinline__ unsigned long long pack2(float lo, float hi) {
    unsigned long long r;
    asm("mov.b64 %0, {%1,%2};" : "=l"(r) : "f"(lo), "f"(hi));
    return r;
}
__device__ __forceinline__ void unpack2(unsigned long long v, float& lo, float& hi) {
    asm("mov.b64 {%0,%1}, %2;" : "=f"(lo), "=f"(hi) : "l"(v));
}
#define FMA2(d, a, b, c) \
    asm("fma.rn.f32x2 %0, %1, %2, %3;" : "=l"(d) : "l"(a), "l"(b), "l"(c))

// float bits -> order-preserving u32 key (handles negatives)
__device__ __forceinline__ unsigned fkey(float f) {
    unsigned b = __float_as_uint(f);
    return b ^ ((unsigned)((int)b >> 31) | 0x80000000u);
}
__device__ __forceinline__ float fkey_inv(unsigned t) {
    unsigned b = (t & 0x80000000u) ? (t ^ 0x80000000u) : ~t;
    return __uint_as_float(b);
}

// sorted top-20 insert, 32-bit dist key + parallel idx array.
// All per-lane insertions happen in ascending candidate-index order, and on
// equal keys the resident (earlier index) stays ahead -> exact jax top_k
// tie semantics (stable sort, earlier index wins, later-index tie evicted).
__device__ __forceinline__ void ins20(unsigned dk, unsigned ii,
                                      unsigned (&kd)[K_NN], unsigned (&id)[K_NN]) {
#pragma unroll
    for (int j = 0; j < K_NN; j++) {
        bool lt = dk < kd[j];
        unsigned nk = lt ? dk : kd[j];
        unsigned ni = lt ? ii : id[j];
        unsigned ck = lt ? kd[j] : dk;
        unsigned ci = lt ? id[j] : ii;
        kd[j] = nk; id[j] = ni;
        dk = ck; ii = ci;
    }
}

// exact reference-rounding distance from scaled point (px2=-2x etc.)
__device__ __forceinline__ float exact_d(float qx, float qy, float qz, float qw,
                                         float4 p) {
    float px = __fmul_rn(-0.5f, p.x);   // exact (power of two scale)
    float py = __fmul_rn(-0.5f, p.y);
    float pz = __fmul_rn(-0.5f, p.z);
    float t = __fadd_rn(__fadd_rn(__fmul_rn(qx, px), __fmul_rn(qy, py)),
                        __fmul_rn(qz, pz));
    return __fsub_rn(__fadd_rn(qw, p.w), __fmul_rn(2.0f, t));
}

// =============================================================================
// Kernel 1: per-batch exact KNN (one query/thread, 4096 candidates in smem)
// FUSED with fp64 BatchNorm moment accumulation (epilogue).
//
// Candidates stored pre-scaled (-2x,-2y,-2z,||x||^2); screen = 3 FFMA vs
// slack threshold. Survivor indices pushed via predicated st.shared to a
// per-lane conflict-free stack. Stack headroom checked once per 32-candidate
// group (warp-uniform), so the hot loop has no limit test. At geometric
// 32-aligned chunk boundaries the stack replays with EXACT reference-rounded
// distances into the sorted 32-bit-keyed top-20.
// =============================================================================
__global__ void __launch_bounds__(512, 1)
knn_stats_kernel(const float* __restrict__ x) {
    extern __shared__ char smem_raw[];
    float4* pts = (float4*)smem_raw;                       // 64 KB
    char*   stacks = smem_raw + N_PTS * sizeof(float4);    // 16*CAP*128 = 64 KB

    const int b    = blockIdx.y;
    const int qblk = blockIdx.x;
    const float* xb = x + (size_t)b * N_PTS * 3;

    for (int i = threadIdx.x; i < N_PTS; i += 512) {
        float x0 = xb[i * 3 + 0], x1 = xb[i * 3 + 1], x2 = xb[i * 3 + 2];
        float sq = __fadd_rn(__fadd_rn(__fmul_rn(x0, x0), __fmul_rn(x1, x1)),
                             __fmul_rn(x2, x2));
        pts[i] = make_float4(__fmul_rn(-2.0f, x0), __fmul_rn(-2.0f, x1),
                             __fmul_rn(-2.0f, x2), sq);
    }
    __syncthreads();

    const int q = qblk * 512 + threadIdx.x;
    const float4 qp = pts[q];
    const float qx = __fmul_rn(-0.5f, qp.x);
    const float qy = __fmul_rn(-0.5f, qp.y);
    const float qz = __fmul_rn(-0.5f, qp.z);
    const float qw = qp.w;

    // per-lane stack addressing (shared address space), 4B slots, 128B stride
    const unsigned sbase =
        (unsigned)__cvta_generic_to_shared(
            stacks + (size_t)(threadIdx.x >> 5) * (CAP * 128)) +
        (threadIdx.x & 31) * 4;
    const unsigned limit = sbase + CAP * 128;
    unsigned addr = sbase;

    unsigned kd[K_NN], id[K_NN];
#pragma unroll
    for (int j = 0; j < K_NN; j++) { kd[j] = 0xFFFFFFFFu; id[j] = 0; }

    // ---- init: candidates 0..19 unconditional, 20..31 gated (exact) ----
#pragma unroll 2
    for (int m = 0; m < K_NN; m++) {
        float d = exact_d(qx, qy, qz, qw, pts[m]);
        ins20(fkey(d), (unsigned)m, kd, id);
    }
#pragma unroll 2
    for (int m = K_NN; m < 32; m++) {
        float d = exact_d(qx, qy, qz, qw, pts[m]);
        unsigned dk = fkey(d);
        if (dk < kd[K_NN - 1]) ins20(dk, (unsigned)m, kd, id);
    }
    float tau = fkey_inv(kd[K_NN - 1]) - qw + SLACK;

    static const short bnd[NCHUNK] = {
        64, 96, 128, 192, 256, 352, 480, 672,
        928, 1280, 1792, 2464, 3392, 4096};

    int lo = 32;
#pragma unroll 1
    for (int c = 0; c < NCHUNK; c++) {
        const int hi = bnd[c];
        // ---- scan in groups of 32 with one headroom check per group ----
#pragma unroll 1
        for (int g = lo; g < hi; g += 32) {
            bool near = (addr + 32u * 128u > limit);
            if (!__any_sync(0xFFFFFFFFu, near)) {
                // fast path: no limit test in the loop
#pragma unroll 8
                for (int mm = 0; mm < 32; mm++) {
                    const int m = g + mm;
                    float4 p = pts[m];
                    float ds = fmaf(p.x, qx, fmaf(p.y, qy, fmaf(p.z, qz, p.w)));
                    asm volatile(
                        "{\n\t"
                        ".reg .pred p;\n\t"
                        "setp.lt.f32 p, %1, %2;\n\t"
                        "@p st.shared.b32 [%0], %3;\n\t"
                        "@p add.u32 %0, %0, 128;\n\t"
                        "}"
                        : "+r"(addr)
                        : "f"(ds), "f"(tau), "r"(m));
                }
            } else {
                // careful path (rare): per-candidate limit test
#pragma unroll 4
                for (int mm = 0; mm < 32; mm++) {
                    const int m = g + mm;
                    float4 p = pts[m];
                    float ds = fmaf(p.x, qx, fmaf(p.y, qy, fmaf(p.z, qz, p.w)));
                    asm volatile(
                        "{\n\t"
                        ".reg .pred p;\n\t"
                        "setp.lt.f32 p, %1, %2;\n\t"
                        "setp.lt.and.u32 p, %0, %3, p;\n\t"
                        "@p st.shared.b32 [%0], %4;\n\t"
                        "@p add.u32 %0, %0, 128;\n\t"
                        "}"
                        : "+r"(addr)
                        : "f"(ds), "f"(tau), "r"(limit), "r"(m));
                }
            }
        }
        // ---- flush: exact recompute + keyed insert (ascending m per lane) ----
        const bool ovf = (addr >= limit);
        const unsigned stop = ovf ? sbase : addr;
        for (unsigned pp = sbase; pp < stop; pp += 128) {
            unsigned m;
            asm volatile("ld.shared.b32 %0, [%1];" : "=r"(m) : "r"(pp));
            float d = exact_d(qx, qy, qz, qw, pts[m]);
            unsigned dk = fkey(d);
            if (dk < kd[K_NN - 1]) ins20(dk, m, kd, id);
        }
        if (__any_sync(0xFFFFFFFFu, ovf)) {      // rare deterministic fallback
            for (int m = lo; m < hi; m++) {
                float d = exact_d(qx, qy, qz, qw, pts[m]);
                unsigned dk = fkey(d);
                if (ovf && dk < kd[K_NN - 1]) ins20(dk, (unsigned)m, kd, id);
            }
        }
        addr = sbase;
        tau = fkey_inv(kd[K_NN - 1]) - qw + SLACK;
        lo = hi;
    }

    // ---- write indices ----
    int* op = g_idx + ((size_t)(b * N_PTS) + q) * K_NN;
#pragma unroll
    for (int j = 0; j < K_NN; j++) op[j] = (int)id[j];

    // ================= fused BN moment epilogue =================
    const float qix = qx, qiy = qy, qiz = qz;
    float sj0 = 0, sj1 = 0, sj2 = 0;
    float jj00 = 0, jj01 = 0, jj02 = 0, jj11 = 0, jj12 = 0, jj22 = 0;
    float ij00 = 0, ij01 = 0, ij02 = 0, ij10 = 0, ij11 = 0, ij12 = 0,
          ij20 = 0, ij21 = 0, ij22 = 0;
#pragma unroll
    for (int j = 0; j < K_NN; j++) {
        float4 p = pts[id[j]];
        float pxx = -0.5f * p.x, pyy = -0.5f * p.y, pzz = -0.5f * p.z;
        sj0 += pxx; sj1 += pyy; sj2 += pzz;
        jj00 = fmaf(pxx, pxx, jj00); jj01 = fmaf(pxx, pyy, jj01);
        jj02 = fmaf(pxx, pzz, jj02); jj11 = fmaf(pyy, pyy, jj11);
        jj12 = fmaf(pyy, pzz, jj12); jj22 = fmaf(pzz, pzz, jj22);
        ij00 = fmaf(qix, pxx, ij00); ij01 = fmaf(qix, pyy, ij01);
        ij02 = fmaf(qix, pzz, ij02); ij10 = fmaf(qiy, pxx, ij10);
        ij11 = fmaf(qiy, pyy, ij11); ij12 = fmaf(qiy, pzz, ij12);
        ij20 = fmaf(qiz, pxx, ij20); ij21 = fmaf(qiz, pyy, ij21);
        ij22 = fmaf(qiz, pzz, ij22);
    }

    double vals[NVALS] = {
        (double)qix, (double)qiy, (double)qiz,
        (double)qix * qix, (double)qix * qiy, (double)qix * qiz,
        (double)qiy * qiy, (double)qiy * qiz, (double)qiz * qiz,
        (double)sj0, (double)sj1, (double)sj2,
        (double)jj00, (double)jj01, (double)jj02,
        (double)jj11, (double)jj12, (double)jj22,
        (double)ij00, (double)ij01, (double)ij02,
        (double)ij10, (double)ij11, (double)ij12,
        (double)ij20, (double)ij21, (double)ij22
    };

    __syncthreads();                       // stacks no longer needed
    double* wsum = (double*)stacks;        // [16][NVALS]
    const int wid = threadIdx.x >> 5;
    const int lid = threadIdx.x & 31;
#pragma unroll
    for (int v = 0; v < NVALS; v++) {
        double s = vals[v];
#pragma unroll
        for (int o = 16; o > 0; o >>= 1) s += __shfl_xor_sync(0xFFFFFFFFu, s, o);
        if (lid == 0) wsum[wid * NVALS + v] = s;
    }
    __syncthreads();
    if (threadIdx.x < NVALS) {
        double s = 0.0;
#pragma unroll
        for (int w = 0; w < 16; w++) s += wsum[w * NVALS + threadIdx.x];
        g_part[(blockIdx.y * gridDim.x + blockIdx.x) * NVALS + threadIdx.x] = s;
    }
}

// =============================================================================
// Kernel 2: finalize BN stats -> per-channel scale/shift (fp64 math).
// =============================================================================
__global__ void __launch_bounds__(864, 1)
finalize_kernel(const float* __restrict__ w1,
                const float* __restrict__ b1,
                const float* __restrict__ gamma,
                const float* __restrict__ beta) {
    __shared__ double S[NVALS];
    const int wid = threadIdx.x >> 5;
    const int lid = threadIdx.x & 31;
    if (wid < NVALS) {
        double s = 0.0;
#pragma unroll
        for (int r = 0; r < KNN_BLOCKS / 32; r++)
            s += g_part[(r * 32 + lid) * NVALS + wid];
#pragma unroll
        for (int o = 16; o > 0; o >>= 1) s += __shfl_xor_sync(0xFFFFFFFFu, s, o);
        if (lid == 0) S[wid] = s;
    }
    __syncthreads();
    if (threadIdx.x >= CO) return;

    const int c = threadIdx.x;
    const double M = (double)B_SZ * N_PTS * K_NN;
    const double Kd = (double)K_NN;

    double q0 = (double)w1[3 * CO + c], q1 = (double)w1[4 * CO + c], q2 = (double)w1[5 * CO + c];
    double p0 = (double)w1[0 * CO + c] - q0;
    double p1 = (double)w1[1 * CO + c] - q1;
    double p2 = (double)w1[2 * CO + c] - q2;
    double s_ = (double)b1[c];

    double Si0 = Kd * S[0], Si1 = Kd * S[1], Si2 = Kd * S[2];
    double i00 = Kd * S[3], i01 = Kd * S[4], i02 = Kd * S[5];
    double i11 = Kd * S[6], i12 = Kd * S[7], i22 = Kd * S[8];
    double Sj0 = S[9], Sj1 = S[10], Sj2 = S[11];
    double j00 = S[12], j01 = S[13], j02 = S[14], j11 = S[15], j12 = S[16], j22 = S[17];

    double pSi = p0 * Si0 + p1 * Si1 + p2 * Si2;
    double qSj = q0 * Sj0 + q1 * Sj1 + q2 * Sj2;
    double mean = (pSi + qSj) / M + s_;

    double pMp = p0 * p0 * i00 + p1 * p1 * i11 + p2 * p2 * i22 +
                 2.0 * (p0 * p1 * i01 + p0 * p2 * i02 + p1 * p2 * i12);
    double qMq = q0 * q0 * j00 + q1 * q1 * j11 + q2 * q2 * j22 +
                 2.0 * (q0 * q1 * j01 + q0 * q2 * j02 + q1 * q2 * j12);
    double pMq = p0 * (q0 * S[18] + q1 * S[19] + q2 * S[20]) +
                 p1 * (q0 * S[21] + q1 * S[22] + q2 * S[23]) +
                 p2 * (q0 * S[24] + q1 * S[25] + q2 * S[26]);

    double sumsq = pMp + qMq + 2.0 * pMq + 2.0 * s_ * (pSi + qSj) + M * s_ * s_;
    double var = sumsq / M - mean * mean;
    double rstd = 1.0 / sqrt(var + 1e-5);

    double g = (double)gamma[c];
    g_scale[c] = (float)(g * rstd);
    g_shift[c] = (float)((double)beta[c] - mean * g * rstd);
}

// =============================================================================
// Kernel 3: fused edge-MLP + BN + ReLU + (r @ w2) + max over K.
// One warp per point, 2 channels/lane. w2 staged pre-duplicated as
// (wa,wa,wb,wb) so stage-2 needs one LDS.128 per c (no repacking).
// =============================================================================
__global__ void __launch_bounds__(256, 3)
main_kernel(const float* __restrict__ x,
            const float* __restrict__ w1,
            const float* __restrict__ b1,
            const float* __restrict__ w2,
            const float* __restrict__ b2,
            float* __restrict__ out) {
    extern __shared__ float sm[];
    ulonglong2* w2d = (ulonglong2*)sm;          // [64][32] x 16B = 32 KB
    float* rt = sm + CO * 32 * 4;               // 8 warps * 64 * 20 floats

    for (int i = threadIdx.x; i < CO * 32; i += blockDim.x) {
        int c = i >> 5, l = i & 31;
        float a = w2[c * CO + l];
        float bb = w2[c * CO + l + 32];
        ulonglong2 v;
        v.x = pack2(a, a);
        v.y = pack2(bb, bb);
        w2d[i] = v;
    }
    __syncthreads();

    const int w = threadIdx.x >> 5;
    const int l = threadIdx.x & 31;
    const int pt = blockIdx.x * 8 + w;
    float* rw = rt + w * (CO * K_NN);

    const int ca = l, cb = l + 32;

    float wja[3], wjb[3], wia[3], wib[3];
#pragma unroll
    for (int r = 0; r < 3; r++) {
        float a0 = __ldg(w1 + r * CO + ca);
        float a3 = __ldg(w1 + (r + 3) * CO + ca);
        float b0 = __ldg(w1 + r * CO + cb);
        float b3 = __ldg(w1 + (r + 3) * CO + cb);
        wja[r] = a3; wjb[r] = b3;
        wia[r] = a0 - a3; wib[r] = b0 - b3;
    }
    const float b1a = __ldg(b1 + ca), b1b = __ldg(b1 + cb);
    const float sca = g_scale[ca], scb = g_scale[cb];
    const float sha = g_shift[ca], shb = g_shift[cb];

    const int b = pt >> 12;
    const int gbase = b << 12;
    const float* xr = x + (size_t)pt * 3;
    const float xi0 = __ldg(xr), xi1 = __ldg(xr + 1), xi2 = __ldg(xr + 2);
    const int* ip = g_idx + (size_t)pt * K_NN;

    const float basea = fmaf(xi2, wia[2], fmaf(xi1, wia[1], fmaf(xi0, wia[0], b1a)));
    const float baseb = fmaf(xi2, wib[2], fmaf(xi1, wib[1], fmaf(xi0, wib[0], b1b)));

    // ---- stage 1: r[c][k] = relu(scale*h + shift) ----
#pragma unroll 4
    for (int k = 0; k < K_NN; k++) {
        int j = __ldg(ip + k);
        const float* xp = x + (size_t)(gbase + j) * 3;
        float j0 = __ldg(xp), j1 = __ldg(xp + 1), j2 = __ldg(xp + 2);

        float ha = fmaf(j2, wja[2], fmaf(j1, wja[1], fmaf(j0, wja[0], basea)));
        float hb = fmaf(j2, wjb[2], fmaf(j1, wjb[1], fmaf(j0, wjb[0], baseb)));

        rw[ca * K_NN + k] = fmaxf(fmaf(ha, sca, sha), 0.0f);
        rw[cb * K_NN + k] = fmaxf(fmaf(hb, scb, shb), 0.0f);
    }
    __syncwarp();

    // ---- stage 2: packed FFMA2 GEMM, acc[i] holds k=(2i, 2i+1) ----
    unsigned long long acca[K_NN / 2], accb[K_NN / 2];
#pragma unroll
    for (int i = 0; i < K_NN / 2; i++) { acca[i] = 0ULL; accb[i] = 0ULL; }

#pragma unroll 4
    for (int c = 0; c < CO; c++) {
        ulonglong2 wab = w2d[c * 32 + l];
        const ulonglong2* r2 = (const ulonglong2*)(rw + c * K_NN);
#pragma unroll
        for (int t = 0; t < 5; t++) {
            ulonglong2 rv = r2[t];
            FMA2(acca[2 * t],     rv.x, wab.x, acca[2 * t]);
            FMA2(acca[2 * t + 1], rv.y, wab.x, acca[2 * t + 1]);
            FMA2(accb[2 * t],     rv.x, wab.y, accb[2 * t]);
            FMA2(accb[2 * t + 1], rv.y, wab.y, accb[2 * t + 1]);
        }
    }

    float ma = -3.402823466e38f, mb = -3.402823466e38f;
#pragma unroll
    for (int i = 0; i < K_NN / 2; i++) {
        float a0, a1, b0, b1v;
        unpack2(acca[i], a0, a1);
        unpack2(accb[i], b0, b1v);
        ma = fmaxf(ma, fmaxf(a0, a1));
        mb = fmaxf(mb, fmaxf(b0, b1v));
    }

    out[(size_t)pt * CO + ca] = ma + __ldg(b2 + ca);
    out[(size_t)pt * CO + cb] = mb + __ldg(b2 + cb);
}

// =============================================================================
extern "C" void kernel_launch(void* const* d_in, const int* in_sizes, int n_in,
                              void* d_out, int out_size) {
    const float* x     = (const float*)d_in[0];
    // d_in[1] = batch indices (implied by layout; unused)
    const float* w1    = (const float*)d_in[2];
    const float* b1    = (const float*)d_in[3];
    const float* gamma = (const float*)d_in[4];
    const float* beta  = (const float*)d_in[5];
    const float* w2    = (const float*)d_in[6];
    const float* b2    = (const float*)d_in[7];
    float* out = (float*)d_out;

    const int knn_smem  = N_PTS * sizeof(float4) + 16 * CAP * 128;          // 128 KB
    const int main_smem = (CO * 32 * 16) + 8 * CO * K_NN * (int)sizeof(float); // 72 KB

    cudaFuncSetAttribute(knn_stats_kernel, cudaFuncAttributeMaxDynamicSharedMemorySize, knn_smem);
    cudaFuncSetAttribute(main_kernel,      cudaFuncAttributeMaxDynamicSharedMemorySize, main_smem);

    knn_stats_kernel<<<dim3(8, B_SZ), 512, knn_smem>>>(x);
    finalize_kernel<<<1, 864>>>(w1, b1, gamma, beta);
    main_kernel<<<(B_SZ * N_PTS) / 8, 256, main_smem>>>(x, w1, b1, w2, b2, out);
}